// round 13
// baseline (speedup 1.0000x reference)
#include <cuda_runtime.h>
#include <math.h>
#include <stdint.h>

#define NN 50000
#define FIN 256
#define HH 2
#define DD 128
#define HD 256          // HH*DD
#define EE 600000
#define ET (EE + NN)    // edges + self loops
#define CC 4

#define BM 128
#define BK 16
#define NBG 782          // gemm blocks: 391 per head * 2 heads
#define NBH 2540         // hist blocks: ceil(650000/256)

// ---------------- scratch (static __device__, no allocations) ----------------
__device__ __align__(16) float g_h1[(size_t)NN * HD];
__device__ float g_es1[NN * HH];
__device__ float g_ed1[NN * HH];
__device__ __align__(16) float g_g2[NN * CC];
__device__ float g_es2[NN];
__device__ float g_ed2[NN];
// CSR structures. g_cnt is zero at module load; scan_kernel re-zeroes it after
// consuming, so "g_cnt == 0 on kernel_launch entry" is a replay-stable invariant.
__device__ int g_cnt[NN];
__device__ int g_rowstart[NN + 1];
__device__ int g_cursor[NN];
__device__ int g_srclist[ET];

// ---------------- helpers ----------------
__device__ __forceinline__ float lrelu(float a) { return a > 0.0f ? a : 0.2f * a; }
__device__ __forceinline__ float elu(float v)   { return v > 0.0f ? v : expm1f(v); }
__device__ __forceinline__ float tf32r(float x) {
    uint32_t r; asm("cvt.rna.tf32.f32 %0, %1;" : "=r"(r) : "f"(x));
    return __uint_as_float(r);
}
__device__ __forceinline__ void mma_tf32(float* d, const float* a, const float* b) {
    asm volatile(
        "mma.sync.aligned.m16n8k8.row.col.f32.tf32.tf32.f32 "
        "{%0,%1,%2,%3}, {%4,%5,%6,%7}, {%8,%9}, {%0,%1,%2,%3};"
        : "+f"(d[0]), "+f"(d[1]), "+f"(d[2]), "+f"(d[3])
        : "r"(__float_as_uint(a[0])), "r"(__float_as_uint(a[1])),
          "r"(__float_as_uint(a[2])), "r"(__float_as_uint(a[3])),
          "r"(__float_as_uint(b[0])), "r"(__float_as_uint(b[1])));
}

// ---------------- combined gemm + attn scores + CSR histogram ----------------
__global__ __launch_bounds__(256, 2)
void gemm_attn_hist_kernel(const float* __restrict__ A, const float* __restrict__ B,
                           const float* __restrict__ a1s, const float* __restrict__ a1d,
                           const int* __restrict__ ei) {
    if (blockIdx.x >= NBG) {
        int e = (blockIdx.x - NBG) * 256 + threadIdx.x;
        if (e < ET) {
            int d = (e < EE) ? ei[EE + e] : (e - EE);
            atomicAdd(&g_cnt[d], 1);
        }
        return;
    }
    __shared__ float As[2][BM][20];
    __shared__ float Bs[2][BK][136];
    __shared__ float sEs[2][BM];
    __shared__ float sEd[2][BM];
    int tid = threadIdx.x;
    int lane = tid & 31, warp = tid >> 5;
    int wr = warp & 3, wc = warp >> 2;
    int gid = lane >> 2, qid = lane & 3;
    int head = blockIdx.x / 391;
    int rowBase = (blockIdx.x % 391) * BM;
    int colBase = head * 128;

    int aRow = tid >> 1, aK = (tid & 1) * 8;
    int bRow = tid >> 4, bCol = (tid & 15) * 8;
    bool aValid = (rowBase + aRow) < NN;
    const float* Ab = A + (size_t)(rowBase + aRow) * FIN + aK;
    const float* Bb = B + (size_t)bRow * HD + colBase + bCol;

    float c[2][8][4] = {};
    float4 zero4 = make_float4(0.f, 0.f, 0.f, 0.f);

    float4 av0 = aValid ? *(const float4*)(Ab)     : zero4;
    float4 av1 = aValid ? *(const float4*)(Ab + 4) : zero4;
    float4 bv0 = *(const float4*)(Bb);
    float4 bv1 = *(const float4*)(Bb + 4);
    {
        float* ap = &As[0][aRow][aK];
        ap[0] = tf32r(av0.x); ap[1] = tf32r(av0.y); ap[2] = tf32r(av0.z); ap[3] = tf32r(av0.w);
        ap[4] = tf32r(av1.x); ap[5] = tf32r(av1.y); ap[6] = tf32r(av1.z); ap[7] = tf32r(av1.w);
        float* bp = &Bs[0][bRow][bCol];
        bp[0] = tf32r(bv0.x); bp[1] = tf32r(bv0.y); bp[2] = tf32r(bv0.z); bp[3] = tf32r(bv0.w);
        bp[4] = tf32r(bv1.x); bp[5] = tf32r(bv1.y); bp[6] = tf32r(bv1.z); bp[7] = tf32r(bv1.w);
    }
    __syncthreads();

    int buf = 0;
    const int NIT = FIN / BK;   // 16
    for (int it = 0; it < NIT; it++) {
        if (it < NIT - 1) {
            int k0 = (it + 1) * BK;
            av0 = aValid ? *(const float4*)(Ab + k0)     : zero4;
            av1 = aValid ? *(const float4*)(Ab + k0 + 4) : zero4;
            bv0 = *(const float4*)(Bb + (size_t)k0 * HD);
            bv1 = *(const float4*)(Bb + (size_t)k0 * HD + 4);
        }
#pragma unroll
        for (int kk = 0; kk < 2; kk++) {
            int kc = kk * 8 + qid;
            float a[2][4], b[8][2];
#pragma unroll
            for (int mt = 0; mt < 2; mt++) {
                int r = wr * 32 + mt * 16 + gid;
                a[mt][0] = As[buf][r][kc];
                a[mt][1] = As[buf][r + 8][kc];
                a[mt][2] = As[buf][r][kc + 4];
                a[mt][3] = As[buf][r + 8][kc + 4];
            }
#pragma unroll
            for (int nt = 0; nt < 8; nt++) {
                int cn = wc * 64 + nt * 8 + gid;
                b[nt][0] = Bs[buf][kk * 8 + qid][cn];
                b[nt][1] = Bs[buf][kk * 8 + qid + 4][cn];
            }
#pragma unroll
            for (int mt = 0; mt < 2; mt++)
#pragma unroll
                for (int nt = 0; nt < 8; nt++)
                    mma_tf32(c[mt][nt], a[mt], b[nt]);
        }
        if (it < NIT - 1) {
            int nxt = buf ^ 1;
            float* ap = &As[nxt][aRow][aK];
            ap[0] = tf32r(av0.x); ap[1] = tf32r(av0.y); ap[2] = tf32r(av0.z); ap[3] = tf32r(av0.w);
            ap[4] = tf32r(av1.x); ap[5] = tf32r(av1.y); ap[6] = tf32r(av1.z); ap[7] = tf32r(av1.w);
            float* bp = &Bs[nxt][bRow][bCol];
            bp[0] = tf32r(bv0.x); bp[1] = tf32r(bv0.y); bp[2] = tf32r(bv0.z); bp[3] = tf32r(bv0.w);
            bp[4] = tf32r(bv1.x); bp[5] = tf32r(bv1.y); bp[6] = tf32r(bv1.z); bp[7] = tf32r(bv1.w);
            __syncthreads();
            buf = nxt;
        }
    }

    // ---- store h1 + fused attention scores ----
    float as0[8], as1[8], ad0[8], ad1[8];
#pragma unroll
    for (int nt = 0; nt < 8; nt++) {
        int cn = wc * 64 + nt * 8 + qid * 2;
        as0[nt] = a1s[head * DD + cn];     as1[nt] = a1s[head * DD + cn + 1];
        ad0[nt] = a1d[head * DD + cn];     ad1[nt] = a1d[head * DD + cn + 1];
    }
    float esA[2] = {0.f, 0.f}, esB[2] = {0.f, 0.f};
    float edA[2] = {0.f, 0.f}, edB[2] = {0.f, 0.f};
#pragma unroll
    for (int mt = 0; mt < 2; mt++) {
#pragma unroll
        for (int nt = 0; nt < 8; nt++) {
            int gr = rowBase + wr * 32 + mt * 16 + gid;
            int col = colBase + wc * 64 + nt * 8 + qid * 2;
            if (gr < NN)
                *(float2*)(g_h1 + (size_t)gr * HD + col) = make_float2(c[mt][nt][0], c[mt][nt][1]);
            if (gr + 8 < NN)
                *(float2*)(g_h1 + (size_t)(gr + 8) * HD + col) = make_float2(c[mt][nt][2], c[mt][nt][3]);
            esA[mt] += c[mt][nt][0] * as0[nt] + c[mt][nt][1] * as1[nt];
            esB[mt] += c[mt][nt][2] * as0[nt] + c[mt][nt][3] * as1[nt];
            edA[mt] += c[mt][nt][0] * ad0[nt] + c[mt][nt][1] * ad1[nt];
            edB[mt] += c[mt][nt][2] * ad0[nt] + c[mt][nt][3] * ad1[nt];
        }
    }
#pragma unroll
    for (int o = 1; o <= 2; o <<= 1) {
#pragma unroll
        for (int mt = 0; mt < 2; mt++) {
            esA[mt] += __shfl_xor_sync(~0u, esA[mt], o);
            esB[mt] += __shfl_xor_sync(~0u, esB[mt], o);
            edA[mt] += __shfl_xor_sync(~0u, edA[mt], o);
            edB[mt] += __shfl_xor_sync(~0u, edB[mt], o);
        }
    }
    if (qid == 0) {
#pragma unroll
        for (int mt = 0; mt < 2; mt++) {
            int rl = wr * 32 + mt * 16 + gid;
            sEs[wc][rl] = esA[mt];     sEd[wc][rl] = edA[mt];
            sEs[wc][rl + 8] = esB[mt]; sEd[wc][rl + 8] = edB[mt];
        }
    }
    __syncthreads();
    if (tid < BM) {
        int gr = rowBase + tid;
        if (gr < NN) {
            g_es1[gr * HH + head] = sEs[0][tid] + sEs[1][tid];
            g_ed1[gr * HH + head] = sEd[0][tid] + sEd[1][tid];
        }
    }
}

// ---------------- CSR scan (also re-zeroes g_cnt for next call) ----------------
#define SCAN_T 1024
__global__ void scan_kernel() {
    __shared__ int sh[SCAN_T];
    int t = threadIdx.x;
    const int CH = (NN + SCAN_T - 1) / SCAN_T;   // 49
    int lo = t * CH;
    int hi = lo + CH; if (hi > NN) hi = NN;
    int sum = 0;
    for (int i = lo; i < hi; i++) sum += g_cnt[i];
    sh[t] = sum;
    __syncthreads();
    for (int off = 1; off < SCAN_T; off <<= 1) {
        int v = (t >= off) ? sh[t - off] : 0;
        __syncthreads();
        sh[t] += v;
        __syncthreads();
    }
    int run = sh[t] - sum;
    for (int i = lo; i < hi; i++) {
        int c = g_cnt[i];
        g_rowstart[i] = run;
        g_cursor[i] = run;
        g_cnt[i] = 0;           // restore zero-invariant for the next replay
        run += c;
    }
    if (t == SCAN_T - 1) g_rowstart[NN] = sh[SCAN_T - 1];
}

__global__ void scatter_kernel(const int* __restrict__ ei) {
    int e = blockIdx.x * blockDim.x + threadIdx.x;
    if (e >= ET) return;
    int s, d;
    if (e < EE) { s = ei[e]; d = ei[EE + e]; }
    else        { s = d = e - EE; }
    int pos = atomicAdd(&g_cursor[d], 1);
    g_srclist[pos] = s;
}

// ---------------- fused layer-1 aggregation + layer-2 transform ----------------
// 2 warps per dst (one per head); edge loop unrolled x2 with independent
// accumulator chains to double gather MLP.
__global__ __launch_bounds__(256)
void aggregate1_fused_kernel(const float* __restrict__ b1,
                             const float* __restrict__ W2,
                             const float* __restrict__ a2s,
                             const float* __restrict__ a2d) {
    __shared__ float sg[8][4];
    int warp = threadIdx.x >> 5;
    int lane = threadIdx.x & 31;
    int d = blockIdx.x * 4 + (warp >> 1);   // NN == 12500*4, always valid
    int head = warp & 1;

    int start = g_rowstart[d], end = g_rowstart[d + 1];
    float edh = g_ed1[d * 2 + head];
    const int colBase = head * DD + lane * 4;

    float4 aA = make_float4(0.f, 0.f, 0.f, 0.f);
    float4 aB = make_float4(0.f, 0.f, 0.f, 0.f);
    float denA = 0.f, denB = 0.f;
    int i = start;
    for (; i + 1 < end; i += 2) {
        int s0 = __ldg(&g_srclist[i]);
        int s1 = __ldg(&g_srclist[i + 1]);
        float w0 = __expf(lrelu(__ldg(&g_es1[s0 * 2 + head]) + edh));
        float w1 = __expf(lrelu(__ldg(&g_es1[s1 * 2 + head]) + edh));
        float4 v0 = __ldg((const float4*)(g_h1 + (size_t)s0 * HD + colBase));
        float4 v1 = __ldg((const float4*)(g_h1 + (size_t)s1 * HD + colBase));
        denA += w0; denB += w1;
        aA.x += v0.x * w0; aA.y += v0.y * w0; aA.z += v0.z * w0; aA.w += v0.w * w0;
        aB.x += v1.x * w1; aB.y += v1.y * w1; aB.z += v1.z * w1; aB.w += v1.w * w1;
    }
    if (i < end) {
        int s0 = __ldg(&g_srclist[i]);
        float w0 = __expf(lrelu(__ldg(&g_es1[s0 * 2 + head]) + edh));
        float4 v0 = __ldg((const float4*)(g_h1 + (size_t)s0 * HD + colBase));
        denA += w0;
        aA.x += v0.x * w0; aA.y += v0.y * w0; aA.z += v0.z * w0; aA.w += v0.w * w0;
    }
    float den = denA + denB;
    float4 a = make_float4(aA.x + aB.x, aA.y + aB.y, aA.z + aB.z, aA.w + aB.w);

    float r = 1.0f / (den + 1e-16f);
    float4 bb = *(const float4*)(b1 + colBase);
    float o0 = elu(a.x * r + bb.x);
    float o1 = elu(a.y * r + bb.y);
    float o2 = elu(a.z * r + bb.z);
    float o3 = elu(a.w * r + bb.w);

    float4 w0v = *(const float4*)(W2 + (colBase + 0) * 4);
    float4 w1v = *(const float4*)(W2 + (colBase + 1) * 4);
    float4 w2v = *(const float4*)(W2 + (colBase + 2) * 4);
    float4 w3v = *(const float4*)(W2 + (colBase + 3) * 4);
    float p0 = o0 * w0v.x + o1 * w1v.x + o2 * w2v.x + o3 * w3v.x;
    float p1 = o0 * w0v.y + o1 * w1v.y + o2 * w2v.y + o3 * w3v.y;
    float p2 = o0 * w0v.z + o1 * w1v.z + o2 * w2v.z + o3 * w3v.z;
    float p3 = o0 * w0v.w + o1 * w1v.w + o2 * w2v.w + o3 * w3v.w;
#pragma unroll
    for (int o = 16; o; o >>= 1) {
        p0 += __shfl_xor_sync(~0u, p0, o);
        p1 += __shfl_xor_sync(~0u, p1, o);
        p2 += __shfl_xor_sync(~0u, p2, o);
        p3 += __shfl_xor_sync(~0u, p3, o);
    }
    if (lane == 0) { sg[warp][0] = p0; sg[warp][1] = p1; sg[warp][2] = p2; sg[warp][3] = p3; }
    __syncthreads();
    if (head == 0 && lane == 0) {
        float g0 = sg[warp][0] + sg[warp + 1][0];
        float g1 = sg[warp][1] + sg[warp + 1][1];
        float g2v = sg[warp][2] + sg[warp + 1][2];
        float g3 = sg[warp][3] + sg[warp + 1][3];
        *(float4*)(g_g2 + d * 4) = make_float4(g0, g1, g2v, g3);
        g_es2[d] = g0 * a2s[0] + g1 * a2s[1] + g2v * a2s[2] + g3 * a2s[3];
        g_ed2[d] = g0 * a2d[0] + g1 * a2d[1] + g2v * a2d[2] + g3 * a2d[3];
    }
}

// ---------------- layer-2 aggregation ----------------
__global__ __launch_bounds__(256)
void aggregate2_kernel(const float* __restrict__ b2, float* __restrict__ out) {
    int d = (blockIdx.x * blockDim.x + threadIdx.x) >> 5;
    int lane = threadIdx.x & 31;
    if (d >= NN) return;
    int start = g_rowstart[d], end = g_rowstart[d + 1];
    float edv = g_ed2[d];

    float den = 0.f;
    float4 a = make_float4(0.f, 0.f, 0.f, 0.f);
    for (int i = start + lane; i < end; i += 32) {
        int s = __ldg(&g_srclist[i]);
        float w = __expf(lrelu(__ldg(&g_es2[s]) + edv));
        den += w;
        const float4 gv = __ldg((const float4*)(g_g2 + s * 4));
        a.x += gv.x * w; a.y += gv.y * w; a.z += gv.z * w; a.w += gv.w * w;
    }
#pragma unroll
    for (int o = 16; o; o >>= 1) {
        a.x += __shfl_xor_sync(~0u, a.x, o);
        a.y += __shfl_xor_sync(~0u, a.y, o);
        a.z += __shfl_xor_sync(~0u, a.z, o);
        a.w += __shfl_xor_sync(~0u, a.w, o);
        den += __shfl_xor_sync(~0u, den, o);
    }
    if (lane == 0) {
        float r = 1.0f / (den + 1e-16f);
        out[d * 4 + 0] = a.x * r + b2[0];
        out[d * 4 + 1] = a.y * r + b2[1];
        out[d * 4 + 2] = a.z * r + b2[2];
        out[d * 4 + 3] = a.w * r + b2[3];
    }
}

// ---------------- launch ----------------
extern "C" void kernel_launch(void* const* d_in, const int* in_sizes, int n_in,
                              void* d_out, int out_size) {
    const float* x    = (const float*)d_in[0];
    const int*   ei   = (const int*)d_in[1];     // edge_index is int32 (JAX x64 disabled)
    const float* W1   = (const float*)d_in[2];
    const float* a1s  = (const float*)d_in[3];
    const float* a1d  = (const float*)d_in[4];
    const float* b1   = (const float*)d_in[5];
    const float* W2   = (const float*)d_in[6];
    const float* a2s  = (const float*)d_in[7];
    const float* a2d  = (const float*)d_in[8];
    const float* b2   = (const float*)d_in[9];
    float* out = (float*)d_out;

    gemm_attn_hist_kernel<<<NBG + NBH, 256>>>(x, W1, a1s, a1d, ei);
    scan_kernel<<<1, SCAN_T>>>();
    scatter_kernel<<<(ET + 255) / 256, 256>>>(ei);
    aggregate1_fused_kernel<<<NN / 4, 256>>>(b1, W2, a2s, a2d);
    aggregate2_kernel<<<(NN * 32 + 255) / 256, 256>>>(b2, out);
}

// round 16
// speedup vs baseline: 1.0072x; 1.0072x over previous
#include <cuda_runtime.h>
#include <math.h>
#include <stdint.h>

#define NN 50000
#define FIN 256
#define HH 2
#define DD 128
#define HD 256          // HH*DD
#define EE 600000
#define ET (EE + NN)    // edges + self loops
#define CC 4

#define BM 128
#define BK 16
#define NBG 782          // gemm blocks: 391 per head * 2 heads
#define NBH 2540         // hist blocks: ceil(650000/256)

// ---------------- scratch (static __device__, no allocations) ----------------
__device__ __align__(16) float g_h1[(size_t)NN * HD];
__device__ float g_es1[NN * HH];
__device__ float g_ed1[NN * HH];
__device__ __align__(16) float g_g2[NN * CC];
__device__ float g_es2[NN];
__device__ float g_ed2[NN];
// CSR structures. g_cnt is zero at module load; scan_kernel re-zeroes it after
// consuming, so "g_cnt == 0 on kernel_launch entry" is a replay-stable invariant.
__device__ int g_cnt[NN];
__device__ int g_rowstart[NN + 1];
__device__ int g_cursor[NN];
__device__ int g_srclist[ET];

// ---------------- helpers ----------------
__device__ __forceinline__ float lrelu(float a) { return a > 0.0f ? a : 0.2f * a; }
__device__ __forceinline__ float elu(float v)   { return v > 0.0f ? v : expm1f(v); }
__device__ __forceinline__ float tf32r(float x) {
    uint32_t r; asm("cvt.rna.tf32.f32 %0, %1;" : "=r"(r) : "f"(x));
    return __uint_as_float(r);
}
__device__ __forceinline__ void mma_tf32(float* d, const float* a, const float* b) {
    asm volatile(
        "mma.sync.aligned.m16n8k8.row.col.f32.tf32.tf32.f32 "
        "{%0,%1,%2,%3}, {%4,%5,%6,%7}, {%8,%9}, {%0,%1,%2,%3};"
        : "+f"(d[0]), "+f"(d[1]), "+f"(d[2]), "+f"(d[3])
        : "r"(__float_as_uint(a[0])), "r"(__float_as_uint(a[1])),
          "r"(__float_as_uint(a[2])), "r"(__float_as_uint(a[3])),
          "r"(__float_as_uint(b[0])), "r"(__float_as_uint(b[1])));
}

// ---------------- combined gemm + attn scores + CSR histogram ----------------
__global__ __launch_bounds__(256, 2)
void gemm_attn_hist_kernel(const float* __restrict__ A, const float* __restrict__ B,
                           const float* __restrict__ a1s, const float* __restrict__ a1d,
                           const int* __restrict__ ei) {
    if (blockIdx.x >= NBG) {
        int e = (blockIdx.x - NBG) * 256 + threadIdx.x;
        if (e < ET) {
            int d = (e < EE) ? ei[EE + e] : (e - EE);
            atomicAdd(&g_cnt[d], 1);
        }
        return;
    }
    __shared__ float As[2][BM][20];
    __shared__ float Bs[2][BK][136];
    __shared__ float sEs[2][BM];
    __shared__ float sEd[2][BM];
    int tid = threadIdx.x;
    int lane = tid & 31, warp = tid >> 5;
    int wr = warp & 3, wc = warp >> 2;
    int gid = lane >> 2, qid = lane & 3;
    int head = blockIdx.x / 391;
    int rowBase = (blockIdx.x % 391) * BM;
    int colBase = head * 128;

    int aRow = tid >> 1, aK = (tid & 1) * 8;
    int bRow = tid >> 4, bCol = (tid & 15) * 8;
    bool aValid = (rowBase + aRow) < NN;
    const float* Ab = A + (size_t)(rowBase + aRow) * FIN + aK;
    const float* Bb = B + (size_t)bRow * HD + colBase + bCol;

    float c[2][8][4] = {};
    float4 zero4 = make_float4(0.f, 0.f, 0.f, 0.f);

    float4 av0 = aValid ? *(const float4*)(Ab)     : zero4;
    float4 av1 = aValid ? *(const float4*)(Ab + 4) : zero4;
    float4 bv0 = *(const float4*)(Bb);
    float4 bv1 = *(const float4*)(Bb + 4);
    {
        float* ap = &As[0][aRow][aK];
        ap[0] = tf32r(av0.x); ap[1] = tf32r(av0.y); ap[2] = tf32r(av0.z); ap[3] = tf32r(av0.w);
        ap[4] = tf32r(av1.x); ap[5] = tf32r(av1.y); ap[6] = tf32r(av1.z); ap[7] = tf32r(av1.w);
        float* bp = &Bs[0][bRow][bCol];
        bp[0] = tf32r(bv0.x); bp[1] = tf32r(bv0.y); bp[2] = tf32r(bv0.z); bp[3] = tf32r(bv0.w);
        bp[4] = tf32r(bv1.x); bp[5] = tf32r(bv1.y); bp[6] = tf32r(bv1.z); bp[7] = tf32r(bv1.w);
    }
    __syncthreads();

    int buf = 0;
    const int NIT = FIN / BK;   // 16
    for (int it = 0; it < NIT; it++) {
        if (it < NIT - 1) {
            int k0 = (it + 1) * BK;
            av0 = aValid ? *(const float4*)(Ab + k0)     : zero4;
            av1 = aValid ? *(const float4*)(Ab + k0 + 4) : zero4;
            bv0 = *(const float4*)(Bb + (size_t)k0 * HD);
            bv1 = *(const float4*)(Bb + (size_t)k0 * HD + 4);
        }
#pragma unroll
        for (int kk = 0; kk < 2; kk++) {
            int kc = kk * 8 + qid;
            float a[2][4], b[8][2];
#pragma unroll
            for (int mt = 0; mt < 2; mt++) {
                int r = wr * 32 + mt * 16 + gid;
                a[mt][0] = As[buf][r][kc];
                a[mt][1] = As[buf][r + 8][kc];
                a[mt][2] = As[buf][r][kc + 4];
                a[mt][3] = As[buf][r + 8][kc + 4];
            }
#pragma unroll
            for (int nt = 0; nt < 8; nt++) {
                int cn = wc * 64 + nt * 8 + gid;
                b[nt][0] = Bs[buf][kk * 8 + qid][cn];
                b[nt][1] = Bs[buf][kk * 8 + qid + 4][cn];
            }
#pragma unroll
            for (int mt = 0; mt < 2; mt++)
#pragma unroll
                for (int nt = 0; nt < 8; nt++)
                    mma_tf32(c[mt][nt], a[mt], b[nt]);
        }
        if (it < NIT - 1) {
            int nxt = buf ^ 1;
            float* ap = &As[nxt][aRow][aK];
            ap[0] = tf32r(av0.x); ap[1] = tf32r(av0.y); ap[2] = tf32r(av0.z); ap[3] = tf32r(av0.w);
            ap[4] = tf32r(av1.x); ap[5] = tf32r(av1.y); ap[6] = tf32r(av1.z); ap[7] = tf32r(av1.w);
            float* bp = &Bs[nxt][bRow][bCol];
            bp[0] = tf32r(bv0.x); bp[1] = tf32r(bv0.y); bp[2] = tf32r(bv0.z); bp[3] = tf32r(bv0.w);
            bp[4] = tf32r(bv1.x); bp[5] = tf32r(bv1.y); bp[6] = tf32r(bv1.z); bp[7] = tf32r(bv1.w);
            __syncthreads();
            buf = nxt;
        }
    }

    // ---- store h1 + fused attention scores ----
    float as0[8], as1[8], ad0[8], ad1[8];
#pragma unroll
    for (int nt = 0; nt < 8; nt++) {
        int cn = wc * 64 + nt * 8 + qid * 2;
        as0[nt] = a1s[head * DD + cn];     as1[nt] = a1s[head * DD + cn + 1];
        ad0[nt] = a1d[head * DD + cn];     ad1[nt] = a1d[head * DD + cn + 1];
    }
    float esA[2] = {0.f, 0.f}, esB[2] = {0.f, 0.f};
    float edA[2] = {0.f, 0.f}, edB[2] = {0.f, 0.f};
#pragma unroll
    for (int mt = 0; mt < 2; mt++) {
#pragma unroll
        for (int nt = 0; nt < 8; nt++) {
            int gr = rowBase + wr * 32 + mt * 16 + gid;
            int col = colBase + wc * 64 + nt * 8 + qid * 2;
            if (gr < NN)
                *(float2*)(g_h1 + (size_t)gr * HD + col) = make_float2(c[mt][nt][0], c[mt][nt][1]);
            if (gr + 8 < NN)
                *(float2*)(g_h1 + (size_t)(gr + 8) * HD + col) = make_float2(c[mt][nt][2], c[mt][nt][3]);
            esA[mt] += c[mt][nt][0] * as0[nt] + c[mt][nt][1] * as1[nt];
            esB[mt] += c[mt][nt][2] * as0[nt] + c[mt][nt][3] * as1[nt];
            edA[mt] += c[mt][nt][0] * ad0[nt] + c[mt][nt][1] * ad1[nt];
            edB[mt] += c[mt][nt][2] * ad0[nt] + c[mt][nt][3] * ad1[nt];
        }
    }
#pragma unroll
    for (int o = 1; o <= 2; o <<= 1) {
#pragma unroll
        for (int mt = 0; mt < 2; mt++) {
            esA[mt] += __shfl_xor_sync(~0u, esA[mt], o);
            esB[mt] += __shfl_xor_sync(~0u, esB[mt], o);
            edA[mt] += __shfl_xor_sync(~0u, edA[mt], o);
            edB[mt] += __shfl_xor_sync(~0u, edB[mt], o);
        }
    }
    if (qid == 0) {
#pragma unroll
        for (int mt = 0; mt < 2; mt++) {
            int rl = wr * 32 + mt * 16 + gid;
            sEs[wc][rl] = esA[mt];     sEd[wc][rl] = edA[mt];
            sEs[wc][rl + 8] = esB[mt]; sEd[wc][rl + 8] = edB[mt];
        }
    }
    __syncthreads();
    if (tid < BM) {
        int gr = rowBase + tid;
        if (gr < NN) {
            g_es1[gr * HH + head] = sEs[0][tid] + sEs[1][tid];
            g_ed1[gr * HH + head] = sEd[0][tid] + sEd[1][tid];
        }
    }
}

// ---------------- CSR scan (also re-zeroes g_cnt for next call) ----------------
#define SCAN_T 1024
__global__ void scan_kernel() {
    __shared__ int sh[SCAN_T];
    int t = threadIdx.x;
    const int CH = (NN + SCAN_T - 1) / SCAN_T;   // 49
    int lo = t * CH;
    int hi = lo + CH; if (hi > NN) hi = NN;
    int sum = 0;
    for (int i = lo; i < hi; i++) sum += g_cnt[i];
    sh[t] = sum;
    __syncthreads();
    for (int off = 1; off < SCAN_T; off <<= 1) {
        int v = (t >= off) ? sh[t - off] : 0;
        __syncthreads();
        sh[t] += v;
        __syncthreads();
    }
    int run = sh[t] - sum;
    for (int i = lo; i < hi; i++) {
        int c = g_cnt[i];
        g_rowstart[i] = run;
        g_cursor[i] = run;
        g_cnt[i] = 0;           // restore zero-invariant for the next replay
        run += c;
    }
    if (t == SCAN_T - 1) g_rowstart[NN] = sh[SCAN_T - 1];
}

__global__ void scatter_kernel(const int* __restrict__ ei) {
    int e = blockIdx.x * blockDim.x + threadIdx.x;
    if (e >= ET) return;
    int s, d;
    if (e < EE) { s = ei[e]; d = ei[EE + e]; }
    else        { s = d = e - EE; }
    int pos = atomicAdd(&g_cursor[d], 1);
    g_srclist[pos] = s;
}

// ---------------- fused layer-1 aggregation + layer-2 transform ----------------
// 2 warps per dst (one per head). Warp-cooperative: per 32-edge chunk, lane j
// computes edge j's weight ONCE; the accumulate loop broadcasts (s, w) via shfl
// and does only the irreducible gather + FMA per edge (kernel was issue-bound
// on 32x-redundant per-lane score/exp computation).
__global__ __launch_bounds__(256)
void aggregate1_fused_kernel(const float* __restrict__ b1,
                             const float* __restrict__ W2,
                             const float* __restrict__ a2s,
                             const float* __restrict__ a2d) {
    __shared__ float sg[8][4];
    int warp = threadIdx.x >> 5;
    int lane = threadIdx.x & 31;
    int d = blockIdx.x * 4 + (warp >> 1);   // NN == 12500*4, always valid
    int head = warp & 1;

    int start = g_rowstart[d], end = g_rowstart[d + 1];
    float edh = g_ed1[d * 2 + head];
    const int colBase = head * DD + lane * 4;

    float4 accA = make_float4(0.f, 0.f, 0.f, 0.f);
    float4 accB = make_float4(0.f, 0.f, 0.f, 0.f);
    float den = 0.f;

    for (int base = start; base < end; base += 32) {
        int n = end - base; if (n > 32) n = 32;
        int s = 0; float w = 0.f;
        if (lane < n) {
            s = g_srclist[base + lane];
            w = __expf(lrelu(g_es1[s * 2 + head] + edh));
        }
        den += w;   // per-lane partial; warp-reduced at the end
        int j = 0;
        for (; j + 1 < n; j += 2) {
            int   s0 = __shfl_sync(~0u, s, j);
            int   s1 = __shfl_sync(~0u, s, j + 1);
            float w0 = __shfl_sync(~0u, w, j);
            float w1 = __shfl_sync(~0u, w, j + 1);
            float4 v0 = *(const float4*)(g_h1 + (size_t)s0 * HD + colBase);
            float4 v1 = *(const float4*)(g_h1 + (size_t)s1 * HD + colBase);
            accA.x += v0.x * w0; accA.y += v0.y * w0; accA.z += v0.z * w0; accA.w += v0.w * w0;
            accB.x += v1.x * w1; accB.y += v1.y * w1; accB.z += v1.z * w1; accB.w += v1.w * w1;
        }
        if (j < n) {
            int   s0 = __shfl_sync(~0u, s, j);
            float w0 = __shfl_sync(~0u, w, j);
            float4 v0 = *(const float4*)(g_h1 + (size_t)s0 * HD + colBase);
            accA.x += v0.x * w0; accA.y += v0.y * w0; accA.z += v0.z * w0; accA.w += v0.w * w0;
        }
    }
#pragma unroll
    for (int o = 16; o; o >>= 1) den += __shfl_xor_sync(~0u, den, o);

    float4 a = make_float4(accA.x + accB.x, accA.y + accB.y,
                           accA.z + accB.z, accA.w + accB.w);
    float r = 1.0f / (den + 1e-16f);
    float4 bb = *(const float4*)(b1 + colBase);
    float o0 = elu(a.x * r + bb.x);
    float o1 = elu(a.y * r + bb.y);
    float o2 = elu(a.z * r + bb.z);
    float o3 = elu(a.w * r + bb.w);

    float4 w0v = *(const float4*)(W2 + (colBase + 0) * 4);
    float4 w1v = *(const float4*)(W2 + (colBase + 1) * 4);
    float4 w2v = *(const float4*)(W2 + (colBase + 2) * 4);
    float4 w3v = *(const float4*)(W2 + (colBase + 3) * 4);
    float p0 = o0 * w0v.x + o1 * w1v.x + o2 * w2v.x + o3 * w3v.x;
    float p1 = o0 * w0v.y + o1 * w1v.y + o2 * w2v.y + o3 * w3v.y;
    float p2 = o0 * w0v.z + o1 * w1v.z + o2 * w2v.z + o3 * w3v.z;
    float p3 = o0 * w0v.w + o1 * w1v.w + o2 * w2v.w + o3 * w3v.w;
#pragma unroll
    for (int o = 16; o; o >>= 1) {
        p0 += __shfl_xor_sync(~0u, p0, o);
        p1 += __shfl_xor_sync(~0u, p1, o);
        p2 += __shfl_xor_sync(~0u, p2, o);
        p3 += __shfl_xor_sync(~0u, p3, o);
    }
    if (lane == 0) { sg[warp][0] = p0; sg[warp][1] = p1; sg[warp][2] = p2; sg[warp][3] = p3; }
    __syncthreads();
    if (head == 0 && lane == 0) {
        float g0 = sg[warp][0] + sg[warp + 1][0];
        float g1 = sg[warp][1] + sg[warp + 1][1];
        float g2v = sg[warp][2] + sg[warp + 1][2];
        float g3 = sg[warp][3] + sg[warp + 1][3];
        *(float4*)(g_g2 + d * 4) = make_float4(g0, g1, g2v, g3);
        g_es2[d] = g0 * a2s[0] + g1 * a2s[1] + g2v * a2s[2] + g3 * a2s[3];
        g_ed2[d] = g0 * a2d[0] + g1 * a2d[1] + g2v * a2d[2] + g3 * a2d[3];
    }
}

// ---------------- layer-2 aggregation ----------------
__global__ __launch_bounds__(256)
void aggregate2_kernel(const float* __restrict__ b2, float* __restrict__ out) {
    int d = (blockIdx.x * blockDim.x + threadIdx.x) >> 5;
    int lane = threadIdx.x & 31;
    if (d >= NN) return;
    int start = g_rowstart[d], end = g_rowstart[d + 1];
    float edv = g_ed2[d];

    float den = 0.f;
    float4 a = make_float4(0.f, 0.f, 0.f, 0.f);
    for (int i = start + lane; i < end; i += 32) {
        int s = g_srclist[i];
        float w = __expf(lrelu(g_es2[s] + edv));
        den += w;
        const float4 gv = *(const float4*)(g_g2 + s * 4);
        a.x += gv.x * w; a.y += gv.y * w; a.z += gv.z * w; a.w += gv.w * w;
    }
#pragma unroll
    for (int o = 16; o; o >>= 1) {
        a.x += __shfl_xor_sync(~0u, a.x, o);
        a.y += __shfl_xor_sync(~0u, a.y, o);
        a.z += __shfl_xor_sync(~0u, a.z, o);
        a.w += __shfl_xor_sync(~0u, a.w, o);
        den += __shfl_xor_sync(~0u, den, o);
    }
    if (lane == 0) {
        float r = 1.0f / (den + 1e-16f);
        out[d * 4 + 0] = a.x * r + b2[0];
        out[d * 4 + 1] = a.y * r + b2[1];
        out[d * 4 + 2] = a.z * r + b2[2];
        out[d * 4 + 3] = a.w * r + b2[3];
    }
}

// ---------------- launch ----------------
extern "C" void kernel_launch(void* const* d_in, const int* in_sizes, int n_in,
                              void* d_out, int out_size) {
    const float* x    = (const float*)d_in[0];
    const int*   ei   = (const int*)d_in[1];     // edge_index is int32 (JAX x64 disabled)
    const float* W1   = (const float*)d_in[2];
    const float* a1s  = (const float*)d_in[3];
    const float* a1d  = (const float*)d_in[4];
    const float* b1   = (const float*)d_in[5];
    const float* W2   = (const float*)d_in[6];
    const float* a2s  = (const float*)d_in[7];
    const float* a2d  = (const float*)d_in[8];
    const float* b2   = (const float*)d_in[9];
    float* out = (float*)d_out;

    gemm_attn_hist_kernel<<<NBG + NBH, 256>>>(x, W1, a1s, a1d, ei);
    scan_kernel<<<1, SCAN_T>>>();
    scatter_kernel<<<(ET + 255) / 256, 256>>>(ei);
    aggregate1_fused_kernel<<<NN / 4, 256>>>(b1, W2, a2s, a2d);
    aggregate2_kernel<<<(NN * 32 + 255) / 256, 256>>>(b2, out);
}